// round 1
// baseline (speedup 1.0000x reference)
#include <cuda_runtime.h>
#include <cstdint>

// ---------------- problem constants ----------------
#define B_   8
#define N_   64
#define NUM_CLASSES 81
#define C_   86           // 4 reg + 1 cent + 81 cls
#define NLEV 5

__constant__ int   c_H[NLEV]    = {128, 64, 32, 16, 8};
__constant__ float c_ps[NLEV]   = {0.0078125f, 0.015625f, 0.03125f, 0.0625f, 0.125f};
__constant__ float c_th0[NLEV]  = {0.0078125f, 0.0625f, 0.125f, 0.25f, 0.5f};
__constant__ float c_th1[NLEV]  = {0.0625f, 0.125f, 0.25f, 0.5f, 1.0f};
// base offset (in floats) of each level in the concatenated output
__constant__ size_t c_base[NLEV] = {0ull, 11272192ull, 14090240ull, 14794752ull, 14970880ull};

// scratch (no allocation allowed)
__device__ float4 g_sboxes[B_][N_];
__device__ int    g_slabels[B_][N_];

// ---------------- kernel 1: stable descending-area sort ----------------
__global__ void sort_kernel(const float* __restrict__ boxes,
                            const int* __restrict__ labels) {
    int b = blockIdx.x;
    int i = threadIdx.x;   // 64 threads
    __shared__ float s_area[N_];

    const float* bx = boxes + ((size_t)b * N_ + i) * 4;
    float x1 = bx[0], y1 = bx[1], x2 = bx[2], y2 = bx[3];
    s_area[i] = (x2 - x1) * (y2 - y1);
    __syncthreads();

    float a = s_area[i];
    int rank = 0;
#pragma unroll
    for (int j = 0; j < N_; j++) {
        float aj = s_area[j];
        // descending by area; stable (ties -> lower original index first)
        rank += (aj > a) || (aj == a && j < i);
    }
    g_sboxes[b][rank]  = make_float4(x1, y1, x2, y2);
    g_slabels[b][rank] = labels[(size_t)b * N_ + i];
}

// ---------------- kernel 2: map levels, 4 pixels per thread ----------------
__global__ __launch_bounds__(256, 4)
void map_kernel(float* __restrict__ out) {
    const int lev = blockIdx.y;
    const int b   = blockIdx.z;
    const int H   = c_H[lev];
    const int HH  = H * H;
    const int ngroups = HH >> 2;           // 4 pixels per thread

    __shared__ float4 sb[N_];
    __shared__ int    sl[N_];
    if (threadIdx.x < N_) {
        sb[threadIdx.x] = g_sboxes[b][threadIdx.x];
        sl[threadIdx.x] = g_slabels[b][threadIdx.x];
    }
    __syncthreads();

    const int g = blockIdx.x * blockDim.x + threadIdx.x;
    if (g >= ngroups) return;

    const float ps  = c_ps[lev];
    const float th0 = c_th0[lev];
    const float th1 = c_th1[lev];

    const int y  = (g << 2) / H;
    const int x0 = (g << 2) % H;
    const float my = ((float)y + 0.5f) * ps;
    float mx[4];
#pragma unroll
    for (int k = 0; k < 4; k++) mx[k] = ((float)(x0 + k) + 0.5f) * ps;

    int  win[4]   = {-1, -1, -1, -1};
    bool fgany[4] = {false, false, false, false};

#pragma unroll 4
    for (int n = 0; n < N_; n++) {
        float4 w = sb[n];
        float t  = my - w.y;
        float bo = w.w - my;
        float mny = fminf(t, bo);
        float mxy = fmaxf(t, bo);
#pragma unroll
        for (int k = 0; k < 4; k++) {
            float l = mx[k] - w.x;
            float r = w.z - mx[k];
            float mn  = fminf(fminf(l, t), fminf(r, bo));
            float mxv = fmaxf(fmaxf(l, t), fmaxf(r, bo));
            (void)mny; (void)mxy;
            bool fg = (mn >= 0.0f);
            fgany[k] |= fg;
            if (fg && (mxv > th0) && (mxv <= th1)) win[k] = n;
        }
    }

    // compute winner-derived outputs per pixel
    float rl[4], rt[4], rr_[4], rb[4], cent[4];
    int   lab[4];
    bool  hw[4];
#pragma unroll
    for (int k = 0; k < 4; k++) {
        hw[k] = (win[k] >= 0);
        if (hw[k]) {
            float4 w = sb[win[k]];
            float l  = mx[k] - w.x;
            float t  = my   - w.y;
            float r  = w.z - mx[k];
            float bo = w.w - my;
            rl[k] = l; rt[k] = t; rr_[k] = r; rb[k] = bo;
            lab[k] = sl[win[k]];
            float dx = fminf(l, r),  Dx = fmaxf(l, r);
            float dy = fminf(t, bo), Dy = fmaxf(t, bo);
            float arg = (dx / (Dx != 0.0f ? Dx : 1.0f)) *
                        (dy / (Dy != 0.0f ? Dy : 1.0f));
            cent[k] = (arg > 0.0f) ? sqrtf(arg) : 0.0f;
        } else {
            rl[k] = rt[k] = rr_[k] = rb[k] = 0.0f;
            cent[k] = 0.0f;
            lab[k] = -1;
        }
    }

    float* rowp = out + c_base[lev] + (size_t)b * C_ * HH + (size_t)y * H + x0;
    const size_t cs = (size_t)HH;

    // reg channels 0..3
    *reinterpret_cast<float4*>(rowp + 0 * cs) = make_float4(rl[0], rl[1], rl[2], rl[3]);
    *reinterpret_cast<float4*>(rowp + 1 * cs) = make_float4(rt[0], rt[1], rt[2], rt[3]);
    *reinterpret_cast<float4*>(rowp + 2 * cs) = make_float4(rr_[0], rr_[1], rr_[2], rr_[3]);
    *reinterpret_cast<float4*>(rowp + 3 * cs) = make_float4(rb[0], rb[1], rb[2], rb[3]);
    // centerness channel 4
    *reinterpret_cast<float4*>(rowp + 4 * cs) = make_float4(cent[0], cent[1], cent[2], cent[3]);

    // cls channels 5..85 (class index cc = 0..80)
    // value = has_win ? (cc==label) : (cc==0 && !fg_any)
    float bg0[4];
#pragma unroll
    for (int k = 0; k < 4; k++) bg0[k] = (!hw[k] && !fgany[k]) ? 1.0f : 0.0f;

#pragma unroll 9
    for (int cc = 0; cc < NUM_CLASSES; cc++) {
        float v[4];
#pragma unroll
        for (int k = 0; k < 4; k++) {
            float on = (lab[k] == cc) ? 1.0f : 0.0f;   // lab==-1 when !hw
            v[k] = hw[k] ? on : (cc == 0 ? bg0[k] : 0.0f);
        }
        *reinterpret_cast<float4*>(rowp + (size_t)(5 + cc) * cs) =
            make_float4(v[0], v[1], v[2], v[3]);
    }
}

extern "C" void kernel_launch(void* const* d_in, const int* in_sizes, int n_in,
                              void* d_out, int out_size) {
    const float* boxes  = (const float*)d_in[0];
    const int*   labels = (const int*)d_in[1];
    float* out = (float*)d_out;

    sort_kernel<<<B_, N_>>>(boxes, labels);

    // largest level: H=128 -> 16384 px -> 4096 groups -> 16 blocks of 256
    dim3 grid(16, NLEV, B_);
    map_kernel<<<grid, 256>>>(out);
}

// round 2
// speedup vs baseline: 1.2441x; 1.2441x over previous
#include <cuda_runtime.h>
#include <cstdint>

// ---------------- problem constants ----------------
#define B_   8
#define N_   64
#define NUM_CLASSES 81
#define C_   86           // 4 reg + 1 cent + 81 cls
#define NLEV 5

__constant__ int   c_H[NLEV]    = {128, 64, 32, 16, 8};
__constant__ float c_ps[NLEV]   = {0.0078125f, 0.015625f, 0.03125f, 0.0625f, 0.125f};
__constant__ float c_th0[NLEV]  = {0.0078125f, 0.0625f, 0.125f, 0.25f, 0.5f};
__constant__ float c_th1[NLEV]  = {0.0625f, 0.125f, 0.25f, 0.5f, 1.0f};
__constant__ size_t c_base[NLEV] = {0ull, 11272192ull, 14090240ull, 14794752ull, 14970880ull};

// scratch (no allocation allowed)
__device__ float4        g_sboxes[B_][N_];
__device__ int           g_slabels[B_][N_];
__device__ unsigned char g_cand[B_][NLEV][N_];
__device__ int           g_ncand[B_][NLEV];

// ---------------- kernel 1: stable descending-area sort + candidate lists ----
__global__ void sort_kernel(const float* __restrict__ boxes,
                            const int* __restrict__ labels) {
    int b = blockIdx.x;
    int i = threadIdx.x;   // 64 threads
    __shared__ float  s_area[N_];
    __shared__ float4 s_sb[N_];

    const float* bx = boxes + ((size_t)b * N_ + i) * 4;
    float x1 = bx[0], y1 = bx[1], x2 = bx[2], y2 = bx[3];
    s_area[i] = (x2 - x1) * (y2 - y1);
    __syncthreads();

    float a = s_area[i];
    int rank = 0;
#pragma unroll
    for (int j = 0; j < N_; j++) {
        float aj = s_area[j];
        rank += (aj > a) || (aj == a && j < i);   // stable descending
    }
    float4 w = make_float4(x1, y1, x2, y2);
    s_sb[rank]         = w;
    g_sboxes[b][rank]  = w;
    g_slabels[b][rank] = labels[(size_t)b * N_ + i];
    __syncthreads();

    // candidate lists: one thread per level
    if (i < NLEV) {
        const int lev = i;
        const float t0 = c_th0[lev] * 0.999f;
        const float t1 = c_th1[lev] * 1.001f;
        int cnt = 0;
        for (int r = 0; r < N_; r++) {
            float4 s = s_sb[r];
            float md = fmaxf(s.z - s.x, s.w - s.y);
            if (md > t0 && 0.5f * md <= t1)
                g_cand[b][lev][cnt++] = (unsigned char)r;
        }
        g_ncand[b][lev] = cnt;
    }
}

// ---------------- kernel 2: map levels, 4 pixels per thread ----------------
__global__ __launch_bounds__(256)
void map_kernel(float* __restrict__ out) {
    const int lev = blockIdx.y;
    const int b   = blockIdx.z;
    const int H   = c_H[lev];
    const int HH  = H * H;
    const int ngroups = HH >> 2;

    __shared__ float4        sb[N_];
    __shared__ int           sl[N_];
    __shared__ unsigned char sc[N_];
    __shared__ int           s_nc;
    if (threadIdx.x < N_) {
        sb[threadIdx.x] = g_sboxes[b][threadIdx.x];
        sl[threadIdx.x] = g_slabels[b][threadIdx.x];
        sc[threadIdx.x] = g_cand[b][lev][threadIdx.x];
    }
    if (threadIdx.x == 0) s_nc = g_ncand[b][lev];
    __syncthreads();

    const int g = blockIdx.x * blockDim.x + threadIdx.x;
    if (g >= ngroups) return;

    const float ps  = c_ps[lev];
    const float th0 = c_th0[lev];
    const float th1 = c_th1[lev];

    const int y  = (g << 2) / H;
    const int x0 = (g << 2) % H;
    const float my = ((float)y + 0.5f) * ps;
    float mx[4];
#pragma unroll
    for (int k = 0; k < 4; k++) mx[k] = ((float)(x0 + k) + 0.5f) * ps;

    // ---- pass A: fg_any over ALL boxes (cheap containment test) ----
    bool f0 = false, f1 = false, f2 = false, f3 = false;
    for (int n = 0; n < N_; n++) {
        float4 w = sb[n];
        if (my >= w.y && my <= w.w) {
            f0 |= (mx[0] >= w.x) && (mx[0] <= w.z);
            f1 |= (mx[1] >= w.x) && (mx[1] <= w.z);
            f2 |= (mx[2] >= w.x) && (mx[2] <= w.z);
            f3 |= (mx[3] >= w.x) && (mx[3] <= w.z);
        }
        if (f0 && f1 && f2 && f3) break;   // monotone OR; sorted big->small saturates fast
    }
    bool fgany[4] = {f0, f1, f2, f3};

    // ---- pass B: winner over candidate boxes only ----
    int win[4] = {-1, -1, -1, -1};
    const int nc = s_nc;
    for (int c = 0; c < nc; c++) {
        const int n = sc[c];
        float4 w = sb[n];
        float t   = my - w.y;
        float bo  = w.w - my;
        float tbn = fminf(t, bo);
        float tbx = fmaxf(t, bo);
#pragma unroll
        for (int k = 0; k < 4; k++) {
            float l   = mx[k] - w.x;
            float r   = w.z - mx[k];
            float mn  = fminf(fminf(l, r), tbn);
            float mxv = fmaxf(fmaxf(l, r), tbx);
            bool pred = (mn >= 0.0f) && (mxv > th0) && (mxv <= th1);
            if (pred) win[k] = n;
        }
    }

    // ---- epilogue: winner-derived values ----
    float rl[4], rt[4], rr_[4], rb[4], cent[4];
    int   lab[4];
    bool  hw[4];
#pragma unroll
    for (int k = 0; k < 4; k++) {
        hw[k] = (win[k] >= 0);
        if (hw[k]) {
            float4 w = sb[win[k]];
            float l  = mx[k] - w.x;
            float t  = my   - w.y;
            float r  = w.z - mx[k];
            float bo = w.w - my;
            rl[k] = l; rt[k] = t; rr_[k] = r; rb[k] = bo;
            lab[k] = sl[win[k]];
            float dx = fminf(l, r),  Dx = fmaxf(l, r);
            float dy = fminf(t, bo), Dy = fmaxf(t, bo);
            float arg = (dx / (Dx != 0.0f ? Dx : 1.0f)) *
                        (dy / (Dy != 0.0f ? Dy : 1.0f));
            cent[k] = (arg > 0.0f) ? sqrtf(arg) : 0.0f;
        } else {
            rl[k] = rt[k] = rr_[k] = rb[k] = 0.0f;
            cent[k] = 0.0f;
            lab[k] = -1;
        }
    }

    float* rowp = out + c_base[lev] + (size_t)b * C_ * HH + (size_t)y * H + x0;
    const size_t cs = (size_t)HH;

    *reinterpret_cast<float4*>(rowp + 0 * cs) = make_float4(rl[0], rl[1], rl[2], rl[3]);
    *reinterpret_cast<float4*>(rowp + 1 * cs) = make_float4(rt[0], rt[1], rt[2], rt[3]);
    *reinterpret_cast<float4*>(rowp + 2 * cs) = make_float4(rr_[0], rr_[1], rr_[2], rr_[3]);
    *reinterpret_cast<float4*>(rowp + 3 * cs) = make_float4(rb[0], rb[1], rb[2], rb[3]);
    *reinterpret_cast<float4*>(rowp + 4 * cs) = make_float4(cent[0], cent[1], cent[2], cent[3]);

    // class channels: zero-fill, then patch
    const float4 z = make_float4(0.0f, 0.0f, 0.0f, 0.0f);
    float* clsp = rowp + 5 * cs;
#pragma unroll 27
    for (int cc = 0; cc < NUM_CLASSES; cc++)
        *reinterpret_cast<float4*>(clsp + (size_t)cc * cs) = z;

#pragma unroll
    for (int k = 0; k < 4; k++) {
        if (hw[k])            clsp[(size_t)lab[k] * cs + k] = 1.0f;  // one-hot
        else if (!fgany[k])   clsp[k] = 1.0f;                        // background (class 0)
    }
}

extern "C" void kernel_launch(void* const* d_in, const int* in_sizes, int n_in,
                              void* d_out, int out_size) {
    const float* boxes  = (const float*)d_in[0];
    const int*   labels = (const int*)d_in[1];
    float* out = (float*)d_out;

    sort_kernel<<<B_, N_>>>(boxes, labels);

    dim3 grid(16, NLEV, B_);
    map_kernel<<<grid, 256>>>(out);
}

// round 3
// speedup vs baseline: 1.3321x; 1.0707x over previous
#include <cuda_runtime.h>
#include <cstdint>

// ---------------- problem constants ----------------
#define B_   8
#define N_   64
#define NUM_CLASSES 81
#define C_   86           // 4 reg + 1 cent + 81 cls
#define NLEV 5

__constant__ int   c_H[NLEV]      = {128, 64, 32, 16, 8};
__constant__ int   c_logH[NLEV]   = {7, 6, 5, 4, 3};
__constant__ int   c_gshift[NLEV] = {12, 10, 8, 6, 4};   // log2(ngroups)
__constant__ float c_ps[NLEV]     = {0.0078125f, 0.015625f, 0.03125f, 0.0625f, 0.125f};
__constant__ float c_th0[NLEV]    = {0.0078125f, 0.0625f, 0.125f, 0.25f, 0.5f};
__constant__ float c_th1[NLEV]    = {0.0625f, 0.125f, 0.25f, 0.5f, 1.0f};
__constant__ size_t c_base[NLEV]  = {0ull, 11272192ull, 14090240ull, 14794752ull, 14970880ull};

// scratch (no allocation allowed)
__device__ float4        g_sboxes[B_][N_];
__device__ int           g_slabels[B_][N_];
__device__ unsigned char g_cand[B_][NLEV][N_];
__device__ int           g_ncand[B_][NLEV];

// ---------------- kernel 1: stable descending-area sort + candidate lists ----
__global__ void sort_kernel(const float* __restrict__ boxes,
                            const int* __restrict__ labels) {
    int b = blockIdx.x;
    int i = threadIdx.x;   // 64 threads
    __shared__ float  s_area[N_];
    __shared__ float4 s_sb[N_];

    const float* bx = boxes + ((size_t)b * N_ + i) * 4;
    float x1 = bx[0], y1 = bx[1], x2 = bx[2], y2 = bx[3];
    s_area[i] = (x2 - x1) * (y2 - y1);
    __syncthreads();

    float a = s_area[i];
    int rank = 0;
#pragma unroll
    for (int j = 0; j < N_; j++) {
        float aj = s_area[j];
        rank += (aj > a) || (aj == a && j < i);   // stable descending
    }
    float4 w = make_float4(x1, y1, x2, y2);
    s_sb[rank]         = w;
    g_sboxes[b][rank]  = w;
    g_slabels[b][rank] = labels[(size_t)b * N_ + i];
    __syncthreads();

    if (i < NLEV) {
        const int lev = i;
        const float t0 = c_th0[lev] * 0.999f;
        const float t1 = c_th1[lev] * 1.001f;
        int cnt = 0;
        for (int r = 0; r < N_; r++) {
            float4 s = s_sb[r];
            float md = fmaxf(s.z - s.x, s.w - s.y);
            if (md > t0 && 0.5f * md <= t1)
                g_cand[b][lev][cnt++] = (unsigned char)r;
        }
        g_ncand[b][lev] = cnt;
    }
}

// ---------------- kernel 2: 4 pixels x channel-slice per thread ----------------
// per batch: lev0 -> 64 blocks, lev1 -> 16, lev2 -> 4, lev3 -> 1, lev4 -> 1
__global__ __launch_bounds__(256)
void map_kernel(float* __restrict__ out) {
    const int b = blockIdx.y;
    const int blk = blockIdx.x;
    int lev, local;
    if (blk < 64)      { lev = 0; local = blk; }
    else if (blk < 80) { lev = 1; local = blk - 64; }
    else if (blk < 84) { lev = 2; local = blk - 80; }
    else if (blk < 85) { lev = 3; local = 0; }
    else               { lev = 4; local = 0; }

    const int H      = c_H[lev];
    const int HH     = H * H;
    const int gshift = c_gshift[lev];
    const int ngroups = HH >> 2;

    __shared__ float4        sb[N_];
    __shared__ int           sl[N_];
    __shared__ unsigned char sc[N_];
    __shared__ int           s_nc;
    if (threadIdx.x < N_) {
        sb[threadIdx.x] = g_sboxes[b][threadIdx.x];
        sl[threadIdx.x] = g_slabels[b][threadIdx.x];
        sc[threadIdx.x] = g_cand[b][lev][threadIdx.x];
    }
    if (threadIdx.x == 0) s_nc = g_ncand[b][lev];
    __syncthreads();

    const int wi = local * 256 + threadIdx.x;
    if (wi >= (ngroups << 2)) return;
    const int s = wi >> gshift;           // channel slice 0..3 (warp-uniform for lev<=3)
    const int g = wi & (ngroups - 1);     // pixel group

    const float ps  = c_ps[lev];
    const float th0 = c_th0[lev];
    const float th1 = c_th1[lev];

    const int gx4 = g << 2;
    const int y   = gx4 >> c_logH[lev];
    const int x0  = gx4 & (H - 1);
    const float my = ((float)y + 0.5f) * ps;
    float mx[4];
#pragma unroll
    for (int k = 0; k < 4; k++) mx[k] = ((float)(x0 + k) + 0.5f) * ps;

    // ---- winner over candidate boxes ----
    int win[4] = {-1, -1, -1, -1};
    const int nc = s_nc;
    for (int c = 0; c < nc; c++) {
        const int n = sc[c];
        float4 w = sb[n];
        float t   = my - w.y;
        float bo  = w.w - my;
        float tbn = fminf(t, bo);
        float tbx = fmaxf(t, bo);
#pragma unroll
        for (int k = 0; k < 4; k++) {
            float l   = mx[k] - w.x;
            float r   = w.z - mx[k];
            float mn  = fminf(fminf(l, r), tbn);
            float mxv = fmaxf(fmaxf(l, r), tbx);
            bool pred = (mn >= 0.0f) && (mxv > th0) && (mxv <= th1);
            if (pred) win[k] = n;
        }
    }

    int  lab[4];
    bool hw[4];
#pragma unroll
    for (int k = 0; k < 4; k++) {
        hw[k]  = (win[k] >= 0);
        lab[k] = hw[k] ? sl[win[k]] : -1;
    }

    float* rowp = out + c_base[lev] + (size_t)b * C_ * HH + (size_t)y * H + x0;
    const size_t cs = (size_t)HH;
    float* clsp = rowp + 5 * cs;
    const float4 z = make_float4(0.0f, 0.0f, 0.0f, 0.0f);

    if (s == 0) {
        // fg_any over ALL boxes (needed for background class only)
        bool f0 = false, f1 = false, f2 = false, f3 = false;
        for (int n = 0; n < N_; n++) {
            float4 w = sb[n];
            if (my >= w.y && my <= w.w) {
                f0 |= (mx[0] >= w.x) && (mx[0] <= w.z);
                f1 |= (mx[1] >= w.x) && (mx[1] <= w.z);
                f2 |= (mx[2] >= w.x) && (mx[2] <= w.z);
                f3 |= (mx[3] >= w.x) && (mx[3] <= w.z);
            }
            if (f0 && f1 && f2 && f3) break;
        }
        bool fgany[4] = {f0, f1, f2, f3};

        // reg + centerness channels
        float rl[4], rt[4], rr_[4], rb[4], cent[4];
#pragma unroll
        for (int k = 0; k < 4; k++) {
            if (hw[k]) {
                float4 w = sb[win[k]];
                float l  = mx[k] - w.x;
                float t  = my   - w.y;
                float r  = w.z - mx[k];
                float bo = w.w - my;
                rl[k] = l; rt[k] = t; rr_[k] = r; rb[k] = bo;
                float dx = fminf(l, r),  Dx = fmaxf(l, r);
                float dy = fminf(t, bo), Dy = fmaxf(t, bo);
                float arg = (dx / (Dx != 0.0f ? Dx : 1.0f)) *
                            (dy / (Dy != 0.0f ? Dy : 1.0f));
                cent[k] = (arg > 0.0f) ? sqrtf(arg) : 0.0f;
            } else {
                rl[k] = rt[k] = rr_[k] = rb[k] = 0.0f;
                cent[k] = 0.0f;
            }
        }
        *reinterpret_cast<float4*>(rowp + 0 * cs) = make_float4(rl[0], rl[1], rl[2], rl[3]);
        *reinterpret_cast<float4*>(rowp + 1 * cs) = make_float4(rt[0], rt[1], rt[2], rt[3]);
        *reinterpret_cast<float4*>(rowp + 2 * cs) = make_float4(rr_[0], rr_[1], rr_[2], rr_[3]);
        *reinterpret_cast<float4*>(rowp + 3 * cs) = make_float4(rb[0], rb[1], rb[2], rb[3]);
        *reinterpret_cast<float4*>(rowp + 4 * cs) = make_float4(cent[0], cent[1], cent[2], cent[3]);

        // class channels 0..16: zero then patch
#pragma unroll 17
        for (int cc = 0; cc < 17; cc++)
            *reinterpret_cast<float4*>(clsp + (size_t)cc * cs) = z;
#pragma unroll
        for (int k = 0; k < 4; k++) {
            if (hw[k]) { if (lab[k] < 17) clsp[(size_t)lab[k] * cs + k] = 1.0f; }
            else if (!fgany[k]) clsp[k] = 1.0f;   // background class 0
        }
    } else {
        // class channels [lo, hi): zero then patch
        const int lo = 17 + (s - 1) * 22;
        const int hi = (s == 3) ? NUM_CLASSES : lo + 22;
#pragma unroll 11
        for (int cc = lo; cc < hi; cc++)
            *reinterpret_cast<float4*>(clsp + (size_t)cc * cs) = z;
#pragma unroll
        for (int k = 0; k < 4; k++)
            if (hw[k] && lab[k] >= lo && lab[k] < hi)
                clsp[(size_t)lab[k] * cs + k] = 1.0f;
    }
}

extern "C" void kernel_launch(void* const* d_in, const int* in_sizes, int n_in,
                              void* d_out, int out_size) {
    const float* boxes  = (const float*)d_in[0];
    const int*   labels = (const int*)d_in[1];
    float* out = (float*)d_out;

    sort_kernel<<<B_, N_>>>(boxes, labels);

    dim3 grid(86, B_);
    map_kernel<<<grid, 256>>>(out);
}